// round 16
// baseline (speedup 1.0000x reference)
#include <cuda_runtime.h>
#include <cstring>

#define NQ     18
#define NREPS  3
#define NBATCH 64
#define IDIM   32

__device__ __forceinline__ float2 cmul(float2 a, float2 b) {
    return make_float2(a.x * b.x - a.y * b.y, a.x * b.y + a.y * b.x);
}
__device__ __forceinline__ float2 cmulc(float2 a, float2 b) {   // a * conj(b)
    return make_float2(a.x * b.x + a.y * b.y, a.y * b.x - a.x * b.y);
}
// packed f32x2 add (sm_100a): one instruction for a complex add
__device__ __forceinline__ float2 cadd(float2 a, float2 b) {
    unsigned long long ua, ub, uo;
    memcpy(&ua, &a, 8); memcpy(&ub, &b, 8);
    asm("add.rn.f32x2 %0, %1, %2;" : "=l"(uo) : "l"(ua), "l"(ub));
    float2 o; memcpy(&o, &uo, 8);
    return o;
}
__device__ __forceinline__ float2 csub(float2 a, float2 b) {
    return make_float2(a.x - b.x, a.y - b.y);
}
__device__ __forceinline__ float2 shflx(float2 v, int m) {
    float2 r;
    r.x = __shfl_xor_sync(0xffffffffu, v.x, m);
    r.y = __shfl_xor_sync(0xffffffffu, v.y, m);
    return r;
}
__device__ __forceinline__ float2 shfl_idx(float2 v, int src) {
    float2 r;
    r.x = __shfl_sync(0xffffffffu, v.x, src);
    r.y = __shfl_sync(0xffffffffu, v.y, src);
    return r;
}
// RY rotation entry: R[i][j] = [[c,-s],[s,c]]
__device__ __forceinline__ float rsel(float c, float s, int i, int j) {
    return (i == j) ? c : (i ? s : -s);
}
// load 8 consecutive float2 (64B, 16B-aligned) as 4x LDS.128
__device__ __forceinline__ void ldrow8(const float2* p, float2* r) {
    const float4* q = (const float4*)p;
    float4 v0 = q[0], v1 = q[1], v2 = q[2], v3 = q[3];
    r[0] = make_float2(v0.x, v0.y); r[1] = make_float2(v0.z, v0.w);
    r[2] = make_float2(v1.x, v1.y); r[3] = make_float2(v1.z, v1.w);
    r[4] = make_float2(v2.x, v2.y); r[5] = make_float2(v2.z, v2.w);
    r[6] = make_float2(v3.x, v3.y); r[7] = make_float2(v3.z, v3.w);
}
// 4-accumulator complex dot: sum_m x[m]*y[m]
__device__ __forceinline__ float2 cdot8(const float2* x, const float2* y) {
    float2 a0 = cmul(x[0], y[0]);
    float2 a1 = cmul(x[1], y[1]);
    float2 a2 = cmul(x[2], y[2]);
    float2 a3 = cmul(x[3], y[3]);
    a0 = cadd(a0, cmul(x[4], y[4]));
    a1 = cadd(a1, cmul(x[5], y[5]));
    a2 = cadd(a2, cmul(x[6], y[6]));
    a3 = cadd(a3, cmul(x[7], y[7]));
    return cadd(cadd(a0, a1), cadd(a2, a3));
}
// 4-accumulator conj dot: sum_m x[m]*conj(y[m])
__device__ __forceinline__ float2 cdot8c(const float2* x, const float2* y) {
    float2 a0 = cmulc(x[0], y[0]);
    float2 a1 = cmulc(x[1], y[1]);
    float2 a2 = cmulc(x[2], y[2]);
    float2 a3 = cmulc(x[3], y[3]);
    a0 = cadd(a0, cmulc(x[4], y[4]));
    a1 = cadd(a1, cmulc(x[5], y[5]));
    a2 = cadd(a2, cmulc(x[6], y[6]));
    a3 = cadd(a3, cmulc(x[7], y[7]));
    return cadd(cadd(a0, a1), cadd(a2, a3));
}

#define HALF_BAR(h) asm volatile("bar.sync %0, %1;" :: "r"(1 + (h)), "r"(256) : "memory")

// Matrix rows padded to 10 float2 (80B); (pr,q) blocks 82 f2. Layout (bytes):
//   [0,      23616)  M  [9][4] blocks of 82 f2, rows [8][10]   (right sweep)
//   [23616,  47232)  MH = M^dagger, same layout                (left sweep)
//   [47232,  70272)  histories rhoH/sigH/Dh/SH [9][8][10] f2 each
//   [70272,  84096)  K (real, 288 rows x 12 floats; dead after setup)
#define SMEM_BYTES 84096

__global__ __launch_bounds__(512, 1) void qenc_kernel(
    const float* __restrict__ xin,   // (64, 32)
    const float* __restrict__ vp,    // (3, 18, 2)
    float* __restrict__ out)         // (64, 18)
{
    extern __shared__ __align__(16) char dyn[];
    float2* Mb    = (float2*)(dyn);
    float2* MHb   = (float2*)(dyn + 23616);
    float2* hist  = (float2*)(dyn + 47232);
    float*  Kb    = (float*)(dyn + 70272);

    __shared__ float sc[NQ][5][2];
    __shared__ float zred[NQ][8];

#define MROW(pr,qq,r)  (Mb  + ((pr)*4+(qq))*82 + (r)*10)
#define MHROW(pr,qq,r) (MHb + ((pr)*4+(qq))*82 + (r)*10)
#define HROW(arr,s,r)  (hist + (arr)*720 + (s)*80 + (r)*10)
#define HEL(arr,s,r,c) hist[(arr)*720 + (s)*80 + (r)*10 + (c)]
#define KROW(rid)      (Kb + (rid) * 12)

    const int b   = blockIdx.x;
    const int tid = threadIdx.x;

    // ---- setup: 5 sincos per site (RY(a)RY(b)=RY(a+b) collapses products) --
    if (tid < NQ * 5) {
        const int k = tid / 5;
        const int g = tid - k * 5;
        float th;
        if (g == 0)      th = vp[(0 * NQ + k) * 2 + 0];
        else if (g == 1) th = vp[(1 * NQ + k) * 2 + 0] + vp[(0 * NQ + k) * 2 + 1];
        else if (g == 2) th = vp[(2 * NQ + k) * 2 + 0] + vp[(1 * NQ + k) * 2 + 1];
        else if (g == 3) th = vp[(2 * NQ + k) * 2 + 1];
        else             th = xin[b * IDIM + k];
        float s, c;
        __sincosf(0.5f * th, &s, &c);
        sc[k][g][0] = c;
        sc[k][g][1] = s;
    }
    __syncthreads();

    // ---- K + M build: warp w handles pair pr = w (warp-local dependency) ---
    if (tid < 288) {
        const int pr  = tid >> 5;
        const int rem = tid & 31;
        const int q   = rem >> 3;
        const int z1 = q >> 1, z2 = q & 1;
        const int k1 = 2 * pr, k2 = 2 * pr + 1;

        // --- K[pr][q][m1][p3p2][n] (REAL; batch-independent) ---
        {
            const int m1  = (rem >> 2) & 1;
            const int p3  = (rem >> 1) & 1;
            const int p2  = rem & 1;
            const float AaC = sc[k1][3][0], AaS = sc[k1][3][1];
            const float AbC = sc[k1][2][0], AbS = sc[k1][2][1];
            const float AcC = sc[k1][1][0], AcS = sc[k1][1][1];
            const float BaC = sc[k2][3][0], BaS = sc[k2][3][1];
            const float BbC = sc[k2][2][0], BbS = sc[k2][2][1];
            const float BcC = sc[k2][1][0], BcS = sc[k2][1][1];
            float t[2][2];
            #pragma unroll
            for (int m3 = 0; m3 < 2; ++m3) {
                const float am3 = rsel(AaC, AaS, z1, m3);
                #pragma unroll
                for (int m2 = 0; m2 < 2; ++m2)
                    t[m3][m2] = am3 * rsel(AbC, AbS, m3 ^ p3, m2)
                                    * rsel(AcC, AcS, m2 ^ p2, m1);
            }
            float in2[2][2][2];
            #pragma unroll
            for (int m3 = 0; m3 < 2; ++m3)
                #pragma unroll
                for (int n2 = 0; n2 < 2; ++n2)
                    #pragma unroll
                    for (int n1 = 0; n1 < 2; ++n1)
                        in2[m3][n2][n1] = t[m3][0] * rsel(BcC, BcS, n2, n1)
                                        + t[m3][1] * rsel(BcC, BcS, n2 ^ 1, n1);
            float outr[8];
            #pragma unroll
            for (int n3 = 0; n3 < 2; ++n3) {
                const float ba = rsel(BaC, BaS, z2, n3);
                #pragma unroll
                for (int n2 = 0; n2 < 2; ++n2)
                    #pragma unroll
                    for (int n1 = 0; n1 < 2; ++n1) {
                        const float v = in2[0][n2][n1] * rsel(BbC, BbS, n3, n2)
                                      + in2[1][n2][n1] * rsel(BbC, BbS, n3 ^ 1, n2);
                        outr[4 * n3 + 2 * n2 + n1] = ba * v;
                    }
            }
            float* kr = KROW(((pr * 4 + q) * 2 + m1) * 4 + (p3 * 2 + p2));
            *(float4*)(kr)     = make_float4(outr[0], outr[1], outr[2], outr[3]);
            *(float4*)(kr + 4) = make_float4(outr[4], outr[5], outr[6], outr[7]);
        }
        __syncwarp();   // M(pr,q,p) reads only this warp's K rows

        // --- M[pr][q][p][n] = sum_{m1} w1[m1^p1] w2[n1^m1] K[m1][p][n] ---
        {
            const int p   = rem & 7;
            const int p1  = p & 1;
            const float c1a = sc[k1][0][0], s1a = sc[k1][0][1];
            const float cxa = sc[k1][4][0], sxa = sc[k1][4][1];
            const float c1b = sc[k2][0][0], s1b = sc[k2][0][1];
            const float cxb = sc[k2][4][0], sxb = sc[k2][4][1];
            float2 w1[2], w2[2];
            w1[0] = make_float2(c1a * cxa,  s1a * sxa);
            w1[1] = make_float2(s1a * cxa, -c1a * sxa);
            w2[0] = make_float2(c1b * cxb,  s1b * sxb);
            w2[1] = make_float2(s1b * cxb, -c1b * sxb);
            const float2 ca0 = cmul(w1[p1], w2[0]);
            const float2 ca1 = cmul(w1[p1], w2[1]);
            const float2 cb0 = cmul(w1[p1 ^ 1], w2[1]);
            const float2 cb1 = cmul(w1[p1 ^ 1], w2[0]);
            const int base = (pr * 4 + q) * 8 + (p >> 1);
            const float* k0r = KROW(base);        // m1 = 0
            const float* k1r = KROW(base + 4);    // m1 = 1
            float4 a0 = *(const float4*)(k0r), a1 = *(const float4*)(k0r + 4);
            float4 b0 = *(const float4*)(k1r), b1 = *(const float4*)(k1r + 4);
            const float K0[8] = {a0.x, a0.y, a0.z, a0.w, a1.x, a1.y, a1.z, a1.w};
            const float K1[8] = {b0.x, b0.y, b0.z, b0.w, b1.x, b1.y, b1.z, b1.w};
            float2* mrow = MROW(pr, q, p);
            #pragma unroll
            for (int n = 0; n < 8; ++n) {
                const float2 cc = (n & 1) ? ca1 : ca0;
                const float2 cd = (n & 1) ? cb1 : cb0;
                const float2 v = make_float2(cc.x * K0[n] + cd.x * K1[n],
                                             cc.y * K0[n] + cd.y * K1[n]);
                mrow[n] = v;
                MHROW(pr, q, n)[p] = make_float2(v.x, -v.y);
            }
        }
    }
    __syncthreads();

    // ---- lane roles: warp = owned row i; lane = (q, a) ----------------------
    const int half = tid >> 8;          // 0 = left sweep, 1 = right sweep
    const int i    = (tid >> 5) & 7;    // warp-in-half = row
    const int lane = tid & 31;
    const int q    = lane >> 3;
    const int a    = lane & 7;
    const int z2   = q & 1;
    const int z1   = q >> 1;
    const int qb   = q * 8;

    // ---- step s = 0 (boundary envs trivial; single stage) -------------------
    {
        float2 t;
        if (half == 0) {
            // rho^(0) = e0 e0^T: t_q[i][a] = M_q[0][i] * conj(M_q[0][a])
            t = cmulc(MHROW(0, q, a)[0], MHROW(0, q, i)[0]);
        } else {
            // sigma^(18) = J: t_q[i][a] = rowsum(M_q,i) * conj(rowsum(M_q,a))
            float2 mi[8], ma[8];
            ldrow8(MROW(8, q, i), mi);
            ldrow8(MROW(8, q, a), ma);
            float2 ri = make_float2(0.f, 0.f), rj = make_float2(0.f, 0.f);
            #pragma unroll
            for (int m = 0; m < 8; ++m) { ri = cadd(ri, mi[m]); rj = cadd(rj, ma[m]); }
            t = cmulc(ri, rj);
        }
        const float2 u    = shflx(t, 8);
        const float2 sum2 = cadd(t, u);
        const float2 dif2 = z2 ? csub(u, t) : csub(t, u);      // t(z2=0)-t(z2=1)
        const float2 s2o  = shflx(sum2, 16);
        const float2 sum4 = cadd(sum2, s2o);
        const float2 d2o  = shflx(dif2, 16);
        const float2 difz2 = cadd(dif2, d2o);
        const float2 difz1 = z1 ? csub(s2o, sum2) : csub(sum2, s2o);
        if (half == 0) {
            if (q == 0)      HEL(0, 1, i, a) = sum4;                            // rho^(2)
            else if (q == 1) HEL(2, 0, i, a) = difz2;                           // D[1]
            else if (q == 2) HEL(0, 0, i, a) = make_float2((i == 0 && a == 0) ? 1.f : 0.f, 0.f);
        } else {
            if (q == 0)      HEL(1, 1, i, a) = sum4;                            // sig^(16)
            else if (q == 1) HEL(3, 0, i, a) = difz1;                           // S[16]
            else if (q == 2) HEL(1, 0, i, a) = make_float2(1.f, 0.f);           // J
        }
    }
    HALF_BAR(half);

    // ---- steps s = 1..8 (unrolled; shuffle-based stage2, no TMP smem) -------
    #pragma unroll
    for (int s = 1; s < 9; ++s) {
        float2 t;
        if (half == 0) {
            // stage1: tl = conj( sum_m MH_q[i][m] * rho[a][m] ) -> lane (q,a)
            float2 r[8], mh[8], mr[8];
            ldrow8(MHROW(s, q, a), mr);     // stage2 row (independent, hoisted)
            ldrow8(HROW(0, s, a), r);
            ldrow8(MHROW(s, q, i), mh);
            const float2 acc = cdot8(mh, r);
            const float2 tl = make_float2(acc.x, -acc.y);
            // stage2: t = sum_{a2} tl(lane q,a2) * MH_q[a][a2]
            float2 t0 = cmul(shfl_idx(tl, qb + 0), mr[0]);
            float2 t1 = cmul(shfl_idx(tl, qb + 1), mr[1]);
            float2 t2 = cmul(shfl_idx(tl, qb + 2), mr[2]);
            float2 t3 = cmul(shfl_idx(tl, qb + 3), mr[3]);
            t0 = cadd(t0, cmul(shfl_idx(tl, qb + 4), mr[4]));
            t1 = cadd(t1, cmul(shfl_idx(tl, qb + 5), mr[5]));
            t2 = cadd(t2, cmul(shfl_idx(tl, qb + 6), mr[6]));
            t3 = cadd(t3, cmul(shfl_idx(tl, qb + 7), mr[7]));
            t = cadd(cadd(t0, t1), cadd(t2, t3));
        } else {
            const int pr = 8 - s;
            // stage1: trr = sum_m M_q[i][m] * conj(sig[a][m]) -> lane (q,a)
            float2 r[8], mi[8], ma[8];
            ldrow8(MROW(pr, q, a), ma);     // stage2 row, hoisted
            ldrow8(HROW(1, s, a), r);
            ldrow8(MROW(pr, q, i), mi);
            const float2 trr = cdot8c(mi, r);
            // stage2: t = sum_{a2} trr(lane q,a2) * conj(M_q[a][a2])
            float2 t0 = cmulc(shfl_idx(trr, qb + 0), ma[0]);
            float2 t1 = cmulc(shfl_idx(trr, qb + 1), ma[1]);
            float2 t2 = cmulc(shfl_idx(trr, qb + 2), ma[2]);
            float2 t3 = cmulc(shfl_idx(trr, qb + 3), ma[3]);
            t0 = cadd(t0, cmulc(shfl_idx(trr, qb + 4), ma[4]));
            t1 = cadd(t1, cmulc(shfl_idx(trr, qb + 5), ma[5]));
            t2 = cadd(t2, cmulc(shfl_idx(trr, qb + 6), ma[6]));
            t3 = cadd(t3, cmulc(shfl_idx(trr, qb + 7), ma[7]));
            t = cadd(cadd(t0, t1), cadd(t2, t3));
        }
        const float2 u    = shflx(t, 8);
        const float2 sum2 = cadd(t, u);
        const float2 dif2 = z2 ? csub(u, t) : csub(t, u);
        const float2 s2o  = shflx(sum2, 16);
        const float2 sum4 = cadd(sum2, s2o);
        const float2 d2o  = shflx(dif2, 16);
        const float2 difz2 = cadd(dif2, d2o);
        const float2 difz1 = z1 ? csub(s2o, sum2) : csub(sum2, s2o);
        if (half == 0) {
            if (q == 0)      { if (s < 8) HEL(0, s + 1, i, a) = sum4; }
            else if (q == 1) HEL(2, s, i, a) = difz2;                  // D[2s+1]
        } else {
            if (q == 0)      { if (s < 8) HEL(1, s + 1, i, a) = sum4; }
            else if (q == 1) HEL(3, s, i, a) = difz1;                  // S[16-2s]
        }
        if (s < 8) HALF_BAR(half);   // last step ordered by the join below
    }
    __syncthreads();   // join halves: epilogue reads both sides' histories

    // ---- observables --------------------------------------------------------
    // even t=2e: Re(rhoH[e] . SH[8-e]);  odd t=2e+1: Re(Dh[e] . sigH[8-e])
    if (tid < NQ * 8) {
        const int w = tid >> 3;
        const int r = tid & 7;
        const int e = w >> 1;
        const float2* dmat = (w & 1) ? HROW(2, e, r)     : HROW(0, e, r);
        const float2* smat = (w & 1) ? HROW(1, 8 - e, r) : HROW(3, 8 - e, r);
        float2 d[8], sm[8];
        ldrow8(dmat, d);
        ldrow8(smat, sm);
        float acc = 0.f;
        #pragma unroll
        for (int j = 0; j < 8; ++j)
            acc += d[j].x * sm[j].x - d[j].y * sm[j].y;
        zred[w][r] = acc;
    }
    __syncthreads();
    if (tid < NQ) {
        float sum = 0.f;
        #pragma unroll
        for (int j = 0; j < 8; ++j) sum += zred[tid][j];
        out[b * NQ + tid] = sum;
    }
}

extern "C" void kernel_launch(void* const* d_in, const int* in_sizes, int n_in,
                              void* d_out, int out_size)
{
    const float* x  = (const float*)d_in[0];   // input_vec (64,32)
    const float* vp = (const float*)d_in[1];   // var_params (3,18,2)
    if (n_in >= 2 && in_sizes[0] == NREPS * NQ * 2) {
        x  = (const float*)d_in[1];
        vp = (const float*)d_in[0];
    }
    cudaFuncSetAttribute(qenc_kernel,
                         cudaFuncAttributeMaxDynamicSharedMemorySize, SMEM_BYTES);
    qenc_kernel<<<NBATCH, 512, SMEM_BYTES>>>(x, vp, (float*)d_out);
}